// round 8
// baseline (speedup 1.0000x reference)
#include <cuda_runtime.h>
#include <cuda_fp16.h>
#include <cstdint>

#define NN 100000
#define NE 1600000
#define NG 64
#define D  64
#define SCAN_B 1024
#define NB_SCAN ((NN + SCAN_B - 1) / SCAN_B)   // 98
#define MT 128                                  // gemm tile rows
#define NBLK_G ((NN + MT - 1) / MT)             // 782

// ---------------- scratch (device globals; no allocation allowed) ----------
__device__ float    g_S[NN * D];      // self-term  X@Wself (fp32)
__device__ float    g_h[NN * D];      // layer-0 output (post-relu)
__device__ __half   g_P[NN * D];      // neighbor-term X@Wneigh (fp16)
__device__ __half   g_Bh[2 * 128 * 64];  // split weights hi, [layer][n][k]
__device__ __half   g_Bl[2 * 128 * 64];  // split weights lo
__device__ int      g_deg[NN];
__device__ int      g_rowStart[NN];
__device__ int      g_cursor[NN];
__device__ int      g_csr[NE];
__device__ int      g_blockSum[NB_SCAN];
__device__ int      g_blockOff[NB_SCAN];
__device__ unsigned g_fEnc[NG * D];

// ---------------- small helpers ---------------------------------------------
__device__ __forceinline__ unsigned encf(float f) {
    unsigned u = __float_as_uint(f);
    return (u & 0x80000000u) ? ~u : (u | 0x80000000u);
}
__device__ __forceinline__ float decf(unsigned u) {
    return __uint_as_float((u & 0x80000000u) ? (u ^ 0x80000000u) : ~u);
}
__device__ __forceinline__ uint32_t pack2(__half a, __half b) {
    __half2 h = __halves2half2(a, b);
    return *reinterpret_cast<uint32_t*>(&h);
}

// m16n8k16 fp16 HMMA, fp32 accumulate in-place (portable PTX, no sm_103a gate)
__device__ __forceinline__ void mma16816(float* d, const uint32_t* a, const uint32_t* b) {
    asm volatile(
        "mma.sync.aligned.m16n8k16.row.col.f32.f16.f16.f32 "
        "{%0,%1,%2,%3}, {%4,%5,%6,%7}, {%8,%9}, {%0,%1,%2,%3};"
        : "+f"(d[0]), "+f"(d[1]), "+f"(d[2]), "+f"(d[3])
        : "r"(a[0]), "r"(a[1]), "r"(a[2]), "r"(a[3]), "r"(b[0]), "r"(b[1]));
}

// ---------------- setup: zero counters + split weights ----------------------
__global__ void k_setup(const float* __restrict__ W0s, const float* __restrict__ W0n,
                        const float* __restrict__ W1s, const float* __restrict__ W1n) {
    int i = blockIdx.x * blockDim.x + threadIdx.x;
    if (i < NN) { g_deg[i] = 0; g_cursor[i] = 0; }
    if (i < NG * D) g_fEnc[i] = 0u;
    if (i < 2 * 128 * 64) {
        int layer = i >> 13;
        int r = i & 8191;
        int n = r >> 6;
        int k = r & 63;
        const float* W = (layer == 0) ? (n < 64 ? W0s : W0n) : (n < 64 ? W1s : W1n);
        float w = W[k * 64 + (n & 63)];
        __half hi = __float2half_rn(w);
        __half lo = __float2half_rn(w - __half2float(hi));
        g_Bh[i] = hi;
        g_Bl[i] = lo;
    }
}

// ---------------- CSR build -------------------------------------------------
__global__ void k_hist(const int* __restrict__ dst) {
    int e = blockIdx.x * blockDim.x + threadIdx.x;
    if (e < NE) atomicAdd(&g_deg[dst[e]], 1);
}

__global__ void k_scan1() {
    __shared__ int s[SCAN_B];
    int t = threadIdx.x;
    int i = blockIdx.x * SCAN_B + t;
    int v = (i < NN) ? g_deg[i] : 0;
    s[t] = v;
    __syncthreads();
    for (int off = 1; off < SCAN_B; off <<= 1) {
        int a = (t >= off) ? s[t - off] : 0;
        __syncthreads();
        s[t] += a;
        __syncthreads();
    }
    if (i < NN) g_rowStart[i] = s[t] - v;
    if (t == SCAN_B - 1) g_blockSum[blockIdx.x] = s[t];
}

__global__ void k_scan2() {          // parallel scan of 98 block sums
    __shared__ int s[128];
    int t = threadIdx.x;
    int v = (t < NB_SCAN) ? g_blockSum[t] : 0;
    s[t] = v;
    __syncthreads();
    for (int off = 1; off < 128; off <<= 1) {
        int a = (t >= off) ? s[t - off] : 0;
        __syncthreads();
        s[t] += a;
        __syncthreads();
    }
    if (t < NB_SCAN) g_blockOff[t] = s[t] - v;
}

__global__ void k_scan3() {
    int i = blockIdx.x * blockDim.x + threadIdx.x;
    if (i < NN) g_rowStart[i] += g_blockOff[i >> 10];
}

__global__ void k_fill(const int* __restrict__ src, const int* __restrict__ dst) {
    int e = blockIdx.x * blockDim.x + threadIdx.x;
    if (e < NE) {
        int d = dst[e];
        int p = atomicAdd(&g_cursor[d], 1);
        g_csr[g_rowStart[d] + p] = src[e];
    }
}

// ---------------- HMMA GEMM: [S|P] = X @ [Wself|Wneigh] ---------------------
// M=128 rows/block (8 warps x 16 rows), N=128, K=64.
// 3-term split-fp16: Ah@Bh + Al@Bh + Ah@Bl  via mma.sync m16n8k16.
// smem word pitch 36 => fragment bank = (4*group + tid4) % 32, conflict-free.
#define PITCH 36
#define AH_W 0
#define AL_W (128 * PITCH)
#define BH_W (2 * 128 * PITCH)
#define BL_W (3 * 128 * PITCH)
#define GEMM_SMEM_B (4 * 128 * PITCH * 4)      // 73728 bytes

template <bool L1>
__global__ __launch_bounds__(256) void k_gemm(const float* __restrict__ Xin) {
    extern __shared__ uint32_t swm[];
    const float* X = L1 ? (const float*)g_h : Xin;
    int t = threadIdx.x;
    int w = t >> 5, lane = t & 31;
    int g = lane >> 2, tid4 = lane & 3;
    int base = blockIdx.x * MT;

    // ---- stage A: fp32 -> split fp16 (hi/lo), padded rows ----
    const float4* X4 = (const float4*)X;
    #pragma unroll
    for (int p = 0; p < 8; p++) {
        int i4 = t + p * 256;                  // float4 index in tile (0..2047)
        int row = i4 >> 4, c4 = i4 & 15;
        int node = base + row;
        float4 v = (node < NN) ? X4[node * 16 + c4] : make_float4(0.f, 0.f, 0.f, 0.f);
        __half h0 = __float2half_rn(v.x), h1 = __float2half_rn(v.y),
               h2 = __float2half_rn(v.z), h3 = __float2half_rn(v.w);
        __half l0 = __float2half_rn(v.x - __half2float(h0));
        __half l1 = __float2half_rn(v.y - __half2float(h1));
        __half l2 = __float2half_rn(v.z - __half2float(h2));
        __half l3 = __float2half_rn(v.w - __half2float(h3));
        int o = row * PITCH + c4 * 2;
        swm[AH_W + o]     = pack2(h0, h1);
        swm[AH_W + o + 1] = pack2(h2, h3);
        swm[AL_W + o]     = pack2(l0, l1);
        swm[AL_W + o + 1] = pack2(l2, l3);
    }
    // ---- stage B: prebuilt split fp16 [n][k] ----
    const uint4* Bh4 = (const uint4*)(g_Bh + (L1 ? 8192 : 0));
    const uint4* Bl4 = (const uint4*)(g_Bl + (L1 ? 8192 : 0));
    #pragma unroll
    for (int p = 0; p < 4; p++) {
        int i = t + p * 256;                   // uint4 index (0..1023)
        int n = i >> 3, q = i & 7;
        *(uint4*)&swm[BH_W + n * PITCH + q * 4] = Bh4[i];
        *(uint4*)&swm[BL_W + n * PITCH + q * 4] = Bl4[i];
    }
    __syncthreads();

    float acc[16][4];
    #pragma unroll
    for (int nt = 0; nt < 16; nt++)
        acc[nt][0] = acc[nt][1] = acc[nt][2] = acc[nt][3] = 0.f;

    int ar0 = (w * 16 + g) * PITCH;
    int ar1 = (w * 16 + g + 8) * PITCH;

    #pragma unroll
    for (int s = 0; s < 4; s++) {              // K = 4 x 16
        int kb = 8 * s;
        uint32_t ah[4], al[4];
        ah[0] = swm[AH_W + ar0 + kb + tid4];
        ah[1] = swm[AH_W + ar1 + kb + tid4];
        ah[2] = swm[AH_W + ar0 + kb + 4 + tid4];
        ah[3] = swm[AH_W + ar1 + kb + 4 + tid4];
        al[0] = swm[AL_W + ar0 + kb + tid4];
        al[1] = swm[AL_W + ar1 + kb + tid4];
        al[2] = swm[AL_W + ar0 + kb + 4 + tid4];
        al[3] = swm[AL_W + ar1 + kb + 4 + tid4];
        #pragma unroll
        for (int nt = 0; nt < 16; nt++) {
            int br = (nt * 8 + g) * PITCH + kb;
            uint32_t bh[2], bl[2];
            bh[0] = swm[BH_W + br + tid4];
            bh[1] = swm[BH_W + br + 4 + tid4];
            bl[0] = swm[BL_W + br + tid4];
            bl[1] = swm[BL_W + br + 4 + tid4];
            mma16816(acc[nt], ah, bh);
            mma16816(acc[nt], al, bh);
            mma16816(acc[nt], ah, bl);
        }
    }

    // ---- epilogue: cols 0..63 -> g_S (fp32), cols 64..127 -> g_P (fp16) ----
    int node0 = base + w * 16 + g;
    int node1 = node0 + 8;
    #pragma unroll
    for (int nt = 0; nt < 8; nt++) {
        int col = nt * 8 + tid4 * 2;
        if (node0 < NN) *(float2*)&g_S[node0 * 64 + col] = make_float2(acc[nt][0], acc[nt][1]);
        if (node1 < NN) *(float2*)&g_S[node1 * 64 + col] = make_float2(acc[nt][2], acc[nt][3]);
    }
    #pragma unroll
    for (int nt = 8; nt < 16; nt++) {
        int col = (nt - 8) * 8 + tid4 * 2;
        if (node0 < NN)
            *(uint32_t*)&g_P[node0 * 64 + col] = pack2(__float2half_rn(acc[nt][0]),
                                                       __float2half_rn(acc[nt][1]));
        if (node1 < NN)
            *(uint32_t*)&g_P[node1 * 64 + col] = pack2(__float2half_rn(acc[nt][2]),
                                                       __float2half_rn(acc[nt][3]));
    }
}

// ---------------- fused aggregation + epilogue (warp-per-node) --------------
// out[n] = S[n] + mean_{u in N(n)} P[u];  layer0: relu -> g_h; layer1: -> E + maxpool
// Warp = 1 node. Lane = (group g = lane>>3) x (chunk c = lane&7).
// Each iteration: 4 edges in flight (one per group), 8 lanes x uint4 cover a
// full 128B P row coalesced. Cross-group reduce via 2 shfl_xor.
template <bool FINAL>
__global__ __launch_bounds__(256) void k_aggfuse(float* __restrict__ E,
                                                 const int* __restrict__ gids) {
    int t = threadIdx.x;
    int wid = t >> 5, lane = t & 31;
    int g = lane >> 3, c = lane & 7;                  // group, column-chunk
    int base = blockIdx.x * 8;
    int n = base + wid;

    int start = g_rowStart[n];
    int deg = g_deg[n];
    const int* __restrict__ lst = g_csr + start;
    const uint4* __restrict__ P4 = (const uint4*)g_P;

    float a[8] = {0.f, 0.f, 0.f, 0.f, 0.f, 0.f, 0.f, 0.f};
    int iters = (deg + 3) >> 2;
    for (int j = 0; j < iters; j++) {
        int e = j * 4 + g;
        if (e < deg) {
            uint4 v = P4[lst[e] * 8 + c];
            float2 f;
            f = __half22float2(*(__half2*)&v.x); a[0] += f.x; a[1] += f.y;
            f = __half22float2(*(__half2*)&v.y); a[2] += f.x; a[3] += f.y;
            f = __half22float2(*(__half2*)&v.z); a[4] += f.x; a[5] += f.y;
            f = __half22float2(*(__half2*)&v.w); a[6] += f.x; a[7] += f.y;
        }
    }
    // reduce across the 4 groups (lanes c, c+8, c+16, c+24)
    #pragma unroll
    for (int q = 0; q < 8; q++) {
        a[q] += __shfl_xor_sync(0xffffffffu, a[q], 8);
        a[q] += __shfl_xor_sync(0xffffffffu, a[q], 16);
    }

    float rd = 1.0f / fmaxf((float)deg, 1.0f);
    float o[8];
    if (g == 0) {                                     // lanes 0..7 finalize
        const float4* S4 = (const float4*)g_S;
        float4 sA = S4[n * 16 + c * 2];
        float4 sB = S4[n * 16 + c * 2 + 1];
        o[0] = sA.x + a[0] * rd; o[1] = sA.y + a[1] * rd;
        o[2] = sA.z + a[2] * rd; o[3] = sA.w + a[3] * rd;
        o[4] = sB.x + a[4] * rd; o[5] = sB.y + a[5] * rd;
        o[6] = sB.z + a[6] * rd; o[7] = sB.w + a[7] * rd;
        if (!FINAL) {
            float4* H4 = (float4*)g_h;
            H4[n * 16 + c * 2]     = make_float4(fmaxf(o[0], 0.f), fmaxf(o[1], 0.f),
                                                 fmaxf(o[2], 0.f), fmaxf(o[3], 0.f));
            H4[n * 16 + c * 2 + 1] = make_float4(fmaxf(o[4], 0.f), fmaxf(o[5], 0.f),
                                                 fmaxf(o[6], 0.f), fmaxf(o[7], 0.f));
        } else {
            float4* E4 = (float4*)E;
            E4[n * 16 + c * 2]     = make_float4(o[0], o[1], o[2], o[3]);
            E4[n * 16 + c * 2 + 1] = make_float4(o[4], o[5], o[6], o[7]);
        }
    }

    if (FINAL) {
        __shared__ unsigned bmax[64];
        if (t < 64) bmax[t] = 0u;
        int g0 = gids[base], g7 = gids[base + 7];
        __syncthreads();
        if (g0 == g7) {                    // whole block = one graph (sorted ids)
            if (g == 0) {
                #pragma unroll
                for (int q = 0; q < 8; q++) atomicMax(&bmax[c * 8 + q], encf(o[q]));
            }
            __syncthreads();
            if (t < 64) atomicMax(&g_fEnc[g0 * 64 + t], bmax[t]);
        } else {                           // rare boundary block: per-node
            if (g == 0) {
                int gn = gids[n];
                #pragma unroll
                for (int q = 0; q < 8; q++)
                    atomicMax(&g_fEnc[gn * 64 + c * 8 + q], encf(o[q]));
            }
        }
    }
}

__global__ void k_decode(float* __restrict__ out) {
    int i = blockIdx.x * blockDim.x + threadIdx.x;
    if (i < NG * D) out[i] = decf(g_fEnc[i]);
}

// ---------------- launch ----------------------------------------------------
extern "C" void kernel_launch(void* const* d_in, const int* in_sizes, int n_in,
                              void* d_out, int out_size) {
    const float* x   = (const float*)d_in[0];
    const int*   src = (const int*)d_in[1];
    const int*   dst = (const int*)d_in[2];
    const int*   gid = (const int*)d_in[3];
    const float* W0s = (const float*)d_in[4];
    const float* W0n = (const float*)d_in[5];
    const float* W1s = (const float*)d_in[6];
    const float* W1n = (const float*)d_in[7];
    float* outF = (float*)d_out;               // [64, 64]
    float* outE = (float*)d_out + NG * D;      // [100000, 64]

    cudaFuncSetAttribute(k_gemm<false>, cudaFuncAttributeMaxDynamicSharedMemorySize, GEMM_SMEM_B);
    cudaFuncSetAttribute(k_gemm<true>,  cudaFuncAttributeMaxDynamicSharedMemorySize, GEMM_SMEM_B);

    // setup (zero counters + split weights) + CSR build
    k_setup <<<(NN + 255) / 256, 256>>>(W0s, W0n, W1s, W1n);
    k_hist  <<<(NE + 255) / 256, 256>>>(dst);
    k_scan1 <<<NB_SCAN, SCAN_B>>>();
    k_scan2 <<<1, 128>>>();
    k_scan3 <<<(NN + 255) / 256, 256>>>();
    k_fill  <<<(NE + 255) / 256, 256>>>(src, dst);

    // layer 0: [S|P] = x @ [W0s|W0n], then h = relu(S + mean-agg(P))
    k_gemm<false><<<NBLK_G, 256, GEMM_SMEM_B>>>(x);
    k_aggfuse<false><<<NN / 8, 256>>>(nullptr, gid);

    // layer 1: [S|P] = h @ [W1s|W1n], then e = S + mean-agg(P), maxpool
    k_gemm<true><<<NBLK_G, 256, GEMM_SMEM_B>>>(nullptr);
    k_aggfuse<true><<<NN / 8, 256>>>(outE, gid);

    k_decode<<<(NG * D + 255) / 256, 256>>>(outF);
}

// round 16
// speedup vs baseline: 1.1631x; 1.1631x over previous
#include <cuda_runtime.h>
#include <cuda_fp16.h>
#include <cstdint>

#define NN 100000
#define NE 1600000
#define NG 64
#define D  64
#define SCAN_B 1024
#define NB_SCAN ((NN + SCAN_B - 1) / SCAN_B)   // 98
#define MT 128                                  // gemm tile rows
#define NBLK_G ((NN + MT - 1) / MT)             // 782

// ---------------- scratch (device globals; no allocation allowed) ----------
__device__ float    g_S[NN * D];      // self-term  X@Wself (fp32)
__device__ float    g_h[NN * D];      // layer-0 output (post-relu)
__device__ __half   g_P[NN * D];      // neighbor-term X@Wneigh (fp16)
__device__ __half   g_Bh[2 * 128 * 64];  // split weights hi, [layer][n][k]
__device__ __half   g_Bl[2 * 128 * 64];  // split weights lo
__device__ int      g_deg[NN];
__device__ int      g_rowStart[NN];   // per-block exclusive (blockOff added by consumers)
__device__ int      g_cursor[NN];
__device__ int      g_csr[NE];
__device__ int      g_blockSum[NB_SCAN];
__device__ int      g_blockOff[NB_SCAN];
__device__ unsigned g_fEnc[NG * D];

// ---------------- small helpers ---------------------------------------------
__device__ __forceinline__ unsigned encf(float f) {
    unsigned u = __float_as_uint(f);
    return (u & 0x80000000u) ? ~u : (u | 0x80000000u);
}
__device__ __forceinline__ float decf(unsigned u) {
    return __uint_as_float((u & 0x80000000u) ? (u ^ 0x80000000u) : ~u);
}
__device__ __forceinline__ uint32_t pack2(__half a, __half b) {
    __half2 h = __halves2half2(a, b);
    return *reinterpret_cast<uint32_t*>(&h);
}

// m16n8k16 fp16 HMMA, fp32 accumulate in-place (portable PTX, no sm_103a gate)
__device__ __forceinline__ void mma16816(float* d, const uint32_t* a, const uint32_t* b) {
    asm volatile(
        "mma.sync.aligned.m16n8k16.row.col.f32.f16.f16.f32 "
        "{%0,%1,%2,%3}, {%4,%5,%6,%7}, {%8,%9}, {%0,%1,%2,%3};"
        : "+f"(d[0]), "+f"(d[1]), "+f"(d[2]), "+f"(d[3])
        : "r"(a[0]), "r"(a[1]), "r"(a[2]), "r"(a[3]), "r"(b[0]), "r"(b[1]));
}

// ---------------- setup: zero counters + split weights ----------------------
__global__ void k_setup(const float* __restrict__ W0s, const float* __restrict__ W0n,
                        const float* __restrict__ W1s, const float* __restrict__ W1n) {
    int i = blockIdx.x * blockDim.x + threadIdx.x;
    if (i < NN) { g_deg[i] = 0; g_cursor[i] = 0; }
    if (i < NG * D) g_fEnc[i] = 0u;
    if (i < 2 * 128 * 64) {
        int layer = i >> 13;
        int r = i & 8191;
        int n = r >> 6;
        int k = r & 63;
        const float* W = (layer == 0) ? (n < 64 ? W0s : W0n) : (n < 64 ? W1s : W1n);
        float w = W[k * 64 + (n & 63)];
        __half hi = __float2half_rn(w);
        __half lo = __float2half_rn(w - __half2float(hi));
        g_Bh[i] = hi;
        g_Bl[i] = lo;
    }
}

// ---------------- CSR build -------------------------------------------------
__global__ void k_hist(const int* __restrict__ dst) {
    int e = blockIdx.x * blockDim.x + threadIdx.x;
    if (e < NE) atomicAdd(&g_deg[dst[e]], 1);
}

__global__ void k_scan1() {
    __shared__ int s[SCAN_B];
    int t = threadIdx.x;
    int i = blockIdx.x * SCAN_B + t;
    int v = (i < NN) ? g_deg[i] : 0;
    s[t] = v;
    __syncthreads();
    for (int off = 1; off < SCAN_B; off <<= 1) {
        int a = (t >= off) ? s[t - off] : 0;
        __syncthreads();
        s[t] += a;
        __syncthreads();
    }
    if (i < NN) g_rowStart[i] = s[t] - v;
    if (t == SCAN_B - 1) g_blockSum[blockIdx.x] = s[t];
}

__global__ void k_scan2() {          // parallel scan of 98 block sums
    __shared__ int s[128];
    int t = threadIdx.x;
    int v = (t < NB_SCAN) ? g_blockSum[t] : 0;
    s[t] = v;
    __syncthreads();
    for (int off = 1; off < 128; off <<= 1) {
        int a = (t >= off) ? s[t - off] : 0;
        __syncthreads();
        s[t] += a;
        __syncthreads();
    }
    if (t < NB_SCAN) g_blockOff[t] = s[t] - v;
}

__global__ void k_fill(const int* __restrict__ src, const int* __restrict__ dst) {
    int e = blockIdx.x * blockDim.x + threadIdx.x;
    if (e < NE) {
        int d = dst[e];
        int p = atomicAdd(&g_cursor[d], 1);
        int base = g_rowStart[d] + g_blockOff[d >> 10];   // inline scan3
        g_csr[base + p] = src[e];
    }
}

// ---------------- HMMA GEMM: [S|P] = X @ [Wself|Wneigh] ---------------------
// M=128 rows/block (8 warps x 16 rows), N=128, K=64.
// 3-term split-fp16: Ah@Bh + Al@Bh + Ah@Bl  via mma.sync m16n8k16.
// smem word pitch 36 => fragment bank = (4*group + tid4) % 32, conflict-free.
#define PITCH 36
#define AH_W 0
#define AL_W (128 * PITCH)
#define BH_W (2 * 128 * PITCH)
#define BL_W (3 * 128 * PITCH)
#define GEMM_SMEM_B (4 * 128 * PITCH * 4)      // 73728 bytes

template <bool L1>
__global__ __launch_bounds__(256) void k_gemm(const float* __restrict__ Xin) {
    extern __shared__ uint32_t swm[];
    const float* X = L1 ? (const float*)g_h : Xin;
    int t = threadIdx.x;
    int w = t >> 5, lane = t & 31;
    int g = lane >> 2, tid4 = lane & 3;
    int base = blockIdx.x * MT;

    // ---- stage A: fp32 -> split fp16 (hi/lo), padded rows ----
    const float4* X4 = (const float4*)X;
    #pragma unroll
    for (int p = 0; p < 8; p++) {
        int i4 = t + p * 256;                  // float4 index in tile (0..2047)
        int row = i4 >> 4, c4 = i4 & 15;
        int node = base + row;
        float4 v = (node < NN) ? X4[node * 16 + c4] : make_float4(0.f, 0.f, 0.f, 0.f);
        __half h0 = __float2half_rn(v.x), h1 = __float2half_rn(v.y),
               h2 = __float2half_rn(v.z), h3 = __float2half_rn(v.w);
        __half l0 = __float2half_rn(v.x - __half2float(h0));
        __half l1 = __float2half_rn(v.y - __half2float(h1));
        __half l2 = __float2half_rn(v.z - __half2float(h2));
        __half l3 = __float2half_rn(v.w - __half2float(h3));
        int o = row * PITCH + c4 * 2;
        swm[AH_W + o]     = pack2(h0, h1);
        swm[AH_W + o + 1] = pack2(h2, h3);
        swm[AL_W + o]     = pack2(l0, l1);
        swm[AL_W + o + 1] = pack2(l2, l3);
    }
    // ---- stage B: prebuilt split fp16 [n][k] ----
    const uint4* Bh4 = (const uint4*)(g_Bh + (L1 ? 8192 : 0));
    const uint4* Bl4 = (const uint4*)(g_Bl + (L1 ? 8192 : 0));
    #pragma unroll
    for (int p = 0; p < 4; p++) {
        int i = t + p * 256;                   // uint4 index (0..1023)
        int n = i >> 3, q = i & 7;
        *(uint4*)&swm[BH_W + n * PITCH + q * 4] = Bh4[i];
        *(uint4*)&swm[BL_W + n * PITCH + q * 4] = Bl4[i];
    }
    __syncthreads();

    float acc[16][4];
    #pragma unroll
    for (int nt = 0; nt < 16; nt++)
        acc[nt][0] = acc[nt][1] = acc[nt][2] = acc[nt][3] = 0.f;

    int ar0 = (w * 16 + g) * PITCH;
    int ar1 = (w * 16 + g + 8) * PITCH;

    #pragma unroll
    for (int s = 0; s < 4; s++) {              // K = 4 x 16
        int kb = 8 * s;
        uint32_t ah[4], al[4];
        ah[0] = swm[AH_W + ar0 + kb + tid4];
        ah[1] = swm[AH_W + ar1 + kb + tid4];
        ah[2] = swm[AH_W + ar0 + kb + 4 + tid4];
        ah[3] = swm[AH_W + ar1 + kb + 4 + tid4];
        al[0] = swm[AL_W + ar0 + kb + tid4];
        al[1] = swm[AL_W + ar1 + kb + tid4];
        al[2] = swm[AL_W + ar0 + kb + 4 + tid4];
        al[3] = swm[AL_W + ar1 + kb + 4 + tid4];
        #pragma unroll
        for (int nt = 0; nt < 16; nt++) {
            int br = (nt * 8 + g) * PITCH + kb;
            uint32_t bh[2], bl[2];
            bh[0] = swm[BH_W + br + tid4];
            bh[1] = swm[BH_W + br + 4 + tid4];
            bl[0] = swm[BL_W + br + tid4];
            bl[1] = swm[BL_W + br + 4 + tid4];
            mma16816(acc[nt], ah, bh);
            mma16816(acc[nt], al, bh);
            mma16816(acc[nt], ah, bl);
        }
    }

    // ---- epilogue: cols 0..63 -> g_S (fp32), cols 64..127 -> g_P (fp16) ----
    int node0 = base + w * 16 + g;
    int node1 = node0 + 8;
    #pragma unroll
    for (int nt = 0; nt < 8; nt++) {
        int col = nt * 8 + tid4 * 2;
        if (node0 < NN) *(float2*)&g_S[node0 * 64 + col] = make_float2(acc[nt][0], acc[nt][1]);
        if (node1 < NN) *(float2*)&g_S[node1 * 64 + col] = make_float2(acc[nt][2], acc[nt][3]);
    }
    #pragma unroll
    for (int nt = 8; nt < 16; nt++) {
        int col = (nt - 8) * 8 + tid4 * 2;
        if (node0 < NN)
            *(uint32_t*)&g_P[node0 * 64 + col] = pack2(__float2half_rn(acc[nt][0]),
                                                       __float2half_rn(acc[nt][1]));
        if (node1 < NN)
            *(uint32_t*)&g_P[node1 * 64 + col] = pack2(__float2half_rn(acc[nt][2]),
                                                       __float2half_rn(acc[nt][3]));
    }
}

// ---------------- fused aggregation + epilogue ------------------------------
// out[n] = S[n] + mean_{u in N(n)} P[u];  layer0: relu -> g_h; layer1: -> E + maxpool
// 8 threads/node (chunk c = t&7), 32 nodes/block. Edge loop unrolled 4x ->
// 4 independent uint4 gathers in flight per thread (MLP=4).
template <bool FINAL>
__global__ __launch_bounds__(256) void k_aggfuse(float* __restrict__ E,
                                                 const int* __restrict__ gids) {
    int t = threadIdx.x;
    int base = blockIdx.x * 32;
    int n = base + (t >> 3);
    int c = t & 7;                                   // cols 8c..8c+7

    int start = g_rowStart[n] + g_blockOff[n >> 10]; // inline scan3
    int deg = g_deg[n];
    const int* __restrict__ lst = g_csr + start;
    const uint4* __restrict__ P4 = (const uint4*)g_P;

    float2 a0 = {0.f, 0.f}, a1 = {0.f, 0.f}, a2 = {0.f, 0.f}, a3 = {0.f, 0.f};
    int j = 0;
    for (; j + 4 <= deg; j += 4) {
        int s0 = lst[j], s1 = lst[j + 1], s2 = lst[j + 2], s3 = lst[j + 3];
        uint4 v0 = P4[s0 * 8 + c];
        uint4 v1 = P4[s1 * 8 + c];
        uint4 v2 = P4[s2 * 8 + c];
        uint4 v3 = P4[s3 * 8 + c];
        float2 f;
        f = __half22float2(*(__half2*)&v0.x); a0.x += f.x; a0.y += f.y;
        f = __half22float2(*(__half2*)&v0.y); a1.x += f.x; a1.y += f.y;
        f = __half22float2(*(__half2*)&v0.z); a2.x += f.x; a2.y += f.y;
        f = __half22float2(*(__half2*)&v0.w); a3.x += f.x; a3.y += f.y;
        f = __half22float2(*(__half2*)&v1.x); a0.x += f.x; a0.y += f.y;
        f = __half22float2(*(__half2*)&v1.y); a1.x += f.x; a1.y += f.y;
        f = __half22float2(*(__half2*)&v1.z); a2.x += f.x; a2.y += f.y;
        f = __half22float2(*(__half2*)&v1.w); a3.x += f.x; a3.y += f.y;
        f = __half22float2(*(__half2*)&v2.x); a0.x += f.x; a0.y += f.y;
        f = __half22float2(*(__half2*)&v2.y); a1.x += f.x; a1.y += f.y;
        f = __half22float2(*(__half2*)&v2.z); a2.x += f.x; a2.y += f.y;
        f = __half22float2(*(__half2*)&v2.w); a3.x += f.x; a3.y += f.y;
        f = __half22float2(*(__half2*)&v3.x); a0.x += f.x; a0.y += f.y;
        f = __half22float2(*(__half2*)&v3.y); a1.x += f.x; a1.y += f.y;
        f = __half22float2(*(__half2*)&v3.z); a2.x += f.x; a2.y += f.y;
        f = __half22float2(*(__half2*)&v3.w); a3.x += f.x; a3.y += f.y;
    }
    for (; j < deg; j++) {
        uint4 v0 = P4[lst[j] * 8 + c];
        float2 f;
        f = __half22float2(*(__half2*)&v0.x); a0.x += f.x; a0.y += f.y;
        f = __half22float2(*(__half2*)&v0.y); a1.x += f.x; a1.y += f.y;
        f = __half22float2(*(__half2*)&v0.z); a2.x += f.x; a2.y += f.y;
        f = __half22float2(*(__half2*)&v0.w); a3.x += f.x; a3.y += f.y;
    }

    float rd = 1.0f / fmaxf((float)deg, 1.0f);
    const float4* S4 = (const float4*)g_S;
    float4 sA = S4[n * 16 + c * 2];
    float4 sB = S4[n * 16 + c * 2 + 1];

    float o0 = sA.x + a0.x * rd, o1 = sA.y + a0.y * rd;
    float o2 = sA.z + a1.x * rd, o3 = sA.w + a1.y * rd;
    float o4 = sB.x + a2.x * rd, o5 = sB.y + a2.y * rd;
    float o6 = sB.z + a3.x * rd, o7 = sB.w + a3.y * rd;

    if (!FINAL) {
        float4* H4 = (float4*)g_h;
        H4[n * 16 + c * 2]     = make_float4(fmaxf(o0, 0.f), fmaxf(o1, 0.f),
                                             fmaxf(o2, 0.f), fmaxf(o3, 0.f));
        H4[n * 16 + c * 2 + 1] = make_float4(fmaxf(o4, 0.f), fmaxf(o5, 0.f),
                                             fmaxf(o6, 0.f), fmaxf(o7, 0.f));
    } else {
        float4* E4 = (float4*)E;
        E4[n * 16 + c * 2]     = make_float4(o0, o1, o2, o3);
        E4[n * 16 + c * 2 + 1] = make_float4(o4, o5, o6, o7);

        __shared__ unsigned bmax[64];
        if (t < 64) bmax[t] = 0u;
        int g0 = gids[base], g31 = gids[base + 31];
        __syncthreads();
        float m[8] = {o0, o1, o2, o3, o4, o5, o6, o7};
        if (g0 == g31) {                       // whole block = one graph (sorted ids)
            #pragma unroll
            for (int q = 0; q < 8; q++) {
                m[q] = fmaxf(m[q], __shfl_xor_sync(0xffffffffu, m[q], 8));
                m[q] = fmaxf(m[q], __shfl_xor_sync(0xffffffffu, m[q], 16));
            }
            if ((t & 31) < 8) {
                #pragma unroll
                for (int q = 0; q < 8; q++) atomicMax(&bmax[c * 8 + q], encf(m[q]));
            }
            __syncthreads();
            if (t < 64) atomicMax(&g_fEnc[g0 * 64 + t], bmax[t]);
        } else {                               // rare boundary block
            int gn = gids[n];
            #pragma unroll
            for (int q = 0; q < 8; q++) atomicMax(&g_fEnc[gn * 64 + c * 8 + q], encf(m[q]));
        }
    }
}

__global__ void k_decode(float* __restrict__ out) {
    int i = blockIdx.x * blockDim.x + threadIdx.x;
    if (i < NG * D) out[i] = decf(g_fEnc[i]);
}

// ---------------- launch ----------------------------------------------------
extern "C" void kernel_launch(void* const* d_in, const int* in_sizes, int n_in,
                              void* d_out, int out_size) {
    const float* x   = (const float*)d_in[0];
    const int*   src = (const int*)d_in[1];
    const int*   dst = (const int*)d_in[2];
    const int*   gid = (const int*)d_in[3];
    const float* W0s = (const float*)d_in[4];
    const float* W0n = (const float*)d_in[5];
    const float* W1s = (const float*)d_in[6];
    const float* W1n = (const float*)d_in[7];
    float* outF = (float*)d_out;               // [64, 64]
    float* outE = (float*)d_out + NG * D;      // [100000, 64]

    cudaFuncSetAttribute(k_gemm<false>, cudaFuncAttributeMaxDynamicSharedMemorySize, GEMM_SMEM_B);
    cudaFuncSetAttribute(k_gemm<true>,  cudaFuncAttributeMaxDynamicSharedMemorySize, GEMM_SMEM_B);

    // setup (zero counters + split weights) + CSR build (scan3 folded into consumers)
    k_setup <<<(NN + 255) / 256, 256>>>(W0s, W0n, W1s, W1n);
    k_hist  <<<(NE + 255) / 256, 256>>>(dst);
    k_scan1 <<<NB_SCAN, SCAN_B>>>();
    k_scan2 <<<1, 128>>>();
    k_fill  <<<(NE + 255) / 256, 256>>>(src, dst);

    // layer 0: [S|P] = x @ [W0s|W0n], then h = relu(S + mean-agg(P))
    k_gemm<false><<<NBLK_G, 256, GEMM_SMEM_B>>>(x);
    k_aggfuse<false><<<NN / 32, 256>>>(nullptr, gid);

    // layer 1: [S|P] = h @ [W1s|W1n], then e = S + mean-agg(P), maxpool
    k_gemm<true><<<NBLK_G, 256, GEMM_SMEM_B>>>(nullptr);
    k_aggfuse<true><<<NN / 32, 256>>>(outE, gid);

    k_decode<<<(NG * D + 255) / 256, 256>>>(outF);
}